// round 1
// baseline (speedup 1.0000x reference)
#include <cuda_runtime.h>
#include <cstdint>

#define N 4096
#define D 256
#define HALF 2048
#define TEMP_INV 0.5f
#define EPS 1e-8f

// ---------------- scratch (device globals; allocation-free) ----------------
__device__ float g_f[N * D];                    // normalized features, 4 MB
__device__ float g_logits[(size_t)N * N];       // sims / T, 64 MB
__device__ float g_part[N];                     // per-row partial results

// ---------------- kernel 1: row-normalize features ----------------
__global__ void k_norm(const float* __restrict__ zi, const float* __restrict__ zj) {
    int r = blockIdx.x;
    const float* src = (r < HALF) ? (zi + (size_t)r * D) : (zj + (size_t)(r - HALF) * D);
    float x = src[threadIdx.x];
    float s = x * x;
    #pragma unroll
    for (int o = 16; o > 0; o >>= 1) s += __shfl_xor_sync(0xffffffffu, s, o);
    __shared__ float ws[8];
    __shared__ float bc;
    if ((threadIdx.x & 31) == 0) ws[threadIdx.x >> 5] = s;
    __syncthreads();
    if (threadIdx.x == 0) {
        float t = 0.f;
        #pragma unroll
        for (int w = 0; w < 8; w++) t += ws[w];
        bc = rsqrtf(t);
    }
    __syncthreads();
    g_f[(size_t)r * D + threadIdx.x] = x * bc;
}

// ---------------- kernel 2: C = f * f^T / TEMP (fp32 tiled GEMM) ----------------
// 128x128 tile, BK=16, 256 threads, 8x8 per thread
__global__ void __launch_bounds__(256) k_gemm() {
    __shared__ float As[16][128];
    __shared__ float Bs[16][128];
    const int tid = threadIdx.x;
    const int tr = tid >> 4;       // 0..15
    const int tc = tid & 15;       // 0..15
    const int i0 = blockIdx.y * 128;
    const int j0 = blockIdx.x * 128;

    float acc[8][8];
    #pragma unroll
    for (int u = 0; u < 8; u++)
        #pragma unroll
        for (int w = 0; w < 8; w++) acc[u][w] = 0.f;

    for (int k0 = 0; k0 < D; k0 += 16) {
        #pragma unroll
        for (int l = 0; l < 2; l++) {
            int lin = tid + l * 256;        // 0..511
            int row = lin >> 2;             // 0..127
            int c4  = lin & 3;              // 0..3
            float4 va = *(const float4*)&g_f[(size_t)(i0 + row) * D + k0 + c4 * 4];
            As[c4 * 4 + 0][row] = va.x;
            As[c4 * 4 + 1][row] = va.y;
            As[c4 * 4 + 2][row] = va.z;
            As[c4 * 4 + 3][row] = va.w;
            float4 vb = *(const float4*)&g_f[(size_t)(j0 + row) * D + k0 + c4 * 4];
            Bs[c4 * 4 + 0][row] = vb.x;
            Bs[c4 * 4 + 1][row] = vb.y;
            Bs[c4 * 4 + 2][row] = vb.z;
            Bs[c4 * 4 + 3][row] = vb.w;
        }
        __syncthreads();
        #pragma unroll
        for (int k = 0; k < 16; k++) {
            float a[8], b[8];
            float4 a0 = *(const float4*)&As[k][tr * 8];
            float4 a1 = *(const float4*)&As[k][tr * 8 + 4];
            float4 b0 = *(const float4*)&Bs[k][tc * 8];
            float4 b1 = *(const float4*)&Bs[k][tc * 8 + 4];
            a[0]=a0.x; a[1]=a0.y; a[2]=a0.z; a[3]=a0.w;
            a[4]=a1.x; a[5]=a1.y; a[6]=a1.z; a[7]=a1.w;
            b[0]=b0.x; b[1]=b0.y; b[2]=b0.z; b[3]=b0.w;
            b[4]=b1.x; b[5]=b1.y; b[6]=b1.z; b[7]=b1.w;
            #pragma unroll
            for (int u = 0; u < 8; u++)
                #pragma unroll
                for (int w = 0; w < 8; w++) acc[u][w] = fmaf(a[u], b[w], acc[u][w]);
        }
        __syncthreads();
    }
    #pragma unroll
    for (int u = 0; u < 8; u++) {
        size_t off = (size_t)(i0 + tr * 8 + u) * N + j0 + tc * 8;
        float4 o0 = make_float4(acc[u][0] * TEMP_INV, acc[u][1] * TEMP_INV,
                                acc[u][2] * TEMP_INV, acc[u][3] * TEMP_INV);
        float4 o1 = make_float4(acc[u][4] * TEMP_INV, acc[u][5] * TEMP_INV,
                                acc[u][6] * TEMP_INV, acc[u][7] * TEMP_INV);
        *(float4*)&g_logits[off]     = o0;
        *(float4*)&g_logits[off + 4] = o1;
    }
}

// ---------------- kernel 3: per-row sort + suffix-sum + logs ----------------
__device__ __forceinline__ float4 load_label(int k, const float* __restrict__ pi,
                                             const float* __restrict__ pj) {
    const float* p = (k < HALF) ? (pi + (size_t)k * 4) : (pj + (size_t)(k - HALF) * 4);
    return __ldg((const float4*)p);
}

__global__ void __launch_bounds__(1024) k_row(const float* __restrict__ pi,
                                              const float* __restrict__ pj) {
    __shared__ unsigned long long kv[N];
    __shared__ float redA[32];
    __shared__ float redB[32];
    __shared__ float bcast[3];   // [0]=rowmax, [1]=rowsum, [2]=diag logit

    const int i = blockIdx.x;
    const int tid = threadIdx.x;
    const int lane = tid & 31;
    const int warp = tid >> 5;

    // load 4 logits for this row
    float4 v = *(const float4*)&g_logits[(size_t)i * N + tid * 4];
    float lmax = fmaxf(fmaxf(v.x, v.y), fmaxf(v.z, v.w));
    float lsum = (v.x + v.y) + (v.z + v.w);
    #pragma unroll
    for (int o = 16; o > 0; o >>= 1) {
        lmax = fmaxf(lmax, __shfl_xor_sync(0xffffffffu, lmax, o));
        lsum += __shfl_xor_sync(0xffffffffu, lsum, o);
    }
    if (lane == 0) { redA[warp] = lmax; redB[warp] = lsum; }
    __syncthreads();
    if (warp == 0) {
        float a = redA[lane];
        float b = redB[lane];
        #pragma unroll
        for (int o = 16; o > 0; o >>= 1) {
            a = fmaxf(a, __shfl_xor_sync(0xffffffffu, a, o));
            b += __shfl_xor_sync(0xffffffffu, b, o);
        }
        if (lane == 0) { bcast[0] = a; bcast[1] = b; }
    }
    __syncthreads();
    const float m = bcast[0];
    const float sumAll = bcast[1];

    float4 li = load_label(i, pi, pj);
    float lg[4] = {v.x, v.y, v.z, v.w};
    #pragma unroll
    for (int q = 0; q < 4; q++) {
        int k = tid * 4 + q;
        unsigned kbits, vbits;
        if (k == i) {
            bcast[2] = lg[q];                 // diagonal logit (before -m)
            kbits = 0x7f800000u;              // +inf -> sorts last
            vbits = 0u;                       // contributes 0 to suffix sums
        } else {
            float4 lk = load_label(k, pi, pj);
            float key = fabsf(li.x - lk.x) + fabsf(li.y - lk.y) +
                        fabsf(li.z - lk.z) + fabsf(li.w - lk.w);
            kbits = __float_as_uint(key);
            vbits = __float_as_uint(__expf(lg[q] - m));
        }
        kv[k] = ((unsigned long long)kbits << 32) | (unsigned long long)vbits;
    }
    __syncthreads();

    // bitonic sort (ascending by key; nonneg float bits order as uints)
    for (int sz = 2; sz <= N; sz <<= 1) {
        for (int st = sz >> 1; st > 0; st >>= 1) {
            #pragma unroll
            for (int it = 0; it < 4; it++) {
                int t = tid + it * 1024;
                int p = t ^ st;
                if (p > t) {
                    unsigned long long a = kv[t];
                    unsigned long long b = kv[p];
                    bool up = ((t & sz) == 0);
                    if ((a > b) == up) { kv[t] = b; kv[p] = a; }
                }
            }
            __syncthreads();
        }
    }

    // inclusive suffix sums of sorted exp values (register-level)
    const int base = tid * 4;
    float v0 = __uint_as_float((unsigned)(kv[base + 0] & 0xffffffffu));
    float v1 = __uint_as_float((unsigned)(kv[base + 1] & 0xffffffffu));
    float v2 = __uint_as_float((unsigned)(kv[base + 2] & 0xffffffffu));
    float v3 = __uint_as_float((unsigned)(kv[base + 3] & 0xffffffffu));
    float s3 = v3;
    float s2 = v2 + s3;
    float s1 = v1 + s2;
    float s0 = v0 + s1;
    float tot = s0;

    // reverse (suffix) inclusive scan across lanes
    float inc = tot;
    #pragma unroll
    for (int o = 1; o < 32; o <<= 1) {
        float y = __shfl_down_sync(0xffffffffu, inc, o);
        if (lane + o < 32) inc += y;
    }
    if (lane == 0) redA[warp] = inc;   // warp total (suffix over whole warp at lane 0)
    __syncthreads();
    if (warp == 0) {
        float x = redA[lane];
        float i2 = x;
        #pragma unroll
        for (int o = 1; o < 32; o <<= 1) {
            float y = __shfl_down_sync(0xffffffffu, i2, o);
            if (lane + o < 32) i2 += y;
        }
        redB[lane] = i2 - x;           // exclusive suffix over warps > lane
    }
    __syncthreads();
    float excl = (inc - tot) + redB[warp];  // sum over all threads with larger tid

    float S0 = s0 + excl;
    float S1 = s1 + excl;
    float S2 = s2 + excl;
    float S3 = s3 + excl;
    float lp = logf(S0 + EPS) + logf(S1 + EPS) + logf(S2 + EPS);
    if (base + 3 < N - 1) lp += logf(S3 + EPS);  // exclude sorted-last (+inf diag)

    // block-sum lp
    #pragma unroll
    for (int o = 16; o > 0; o >>= 1) lp += __shfl_xor_sync(0xffffffffu, lp, o);
    if (lane == 0) redA[warp] = lp;
    __syncthreads();
    if (warp == 0) {
        float x = redA[lane];
        #pragma unroll
        for (int o = 16; o > 0; o >>= 1) x += __shfl_xor_sync(0xffffffffu, x, o);
        if (lane == 0) {
            float diag = bcast[2];
            float sumlogit = (sumAll - (float)N * m) - (diag - m);
            g_part[i] = sumlogit - x;
        }
    }
}

// ---------------- kernel 4: deterministic final reduce ----------------
__global__ void __launch_bounds__(1024) k_final(float* __restrict__ out) {
    const int tid = threadIdx.x;
    const int lane = tid & 31;
    const int warp = tid >> 5;
    float4 p = *(const float4*)&g_part[tid * 4];
    float s = (p.x + p.y) + (p.z + p.w);
    #pragma unroll
    for (int o = 16; o > 0; o >>= 1) s += __shfl_xor_sync(0xffffffffu, s, o);
    __shared__ float ws[32];
    if (lane == 0) ws[warp] = s;
    __syncthreads();
    if (warp == 0) {
        float x = ws[lane];
        #pragma unroll
        for (int o = 16; o > 0; o >>= 1) x += __shfl_xor_sync(0xffffffffu, x, o);
        if (lane == 0) out[0] = -x / ((float)N * (float)(N - 1));
    }
}

// ---------------- entry ----------------
extern "C" void kernel_launch(void* const* d_in, const int* in_sizes, int n_in,
                              void* d_out, int out_size) {
    const float* zi = (const float*)d_in[0];
    const float* zj = (const float*)d_in[1];
    const float* pi = (const float*)d_in[2];
    const float* pj = (const float*)d_in[3];
    (void)in_sizes; (void)n_in; (void)out_size;

    k_norm<<<N, 256>>>(zi, zj);
    k_gemm<<<dim3(N / 128, N / 128), 256>>>();
    k_row<<<N, 1024>>>(pi, pj);
    k_final<<<1, 1024>>>((float*)d_out);
}

// round 2
// speedup vs baseline: 2.6721x; 2.6721x over previous
#include <cuda_runtime.h>
#include <cstdint>

#define N 4096
#define D 256
#define HALF 2048
#define EPS 1e-8f

// ---------------- scratch (device globals; allocation-free) ----------------
__device__ float g_f[N * D];                    // normalized features * sqrt(1/T), 4 MB
__device__ float g_logits[(size_t)N * N];       // sims / T, 64 MB
__device__ float g_part[N];                     // per-row partial results

// ---------------- kernel 1: row-normalize features (folds 1/T) ----------------
__global__ void k_norm(const float* __restrict__ zi, const float* __restrict__ zj) {
    int r = blockIdx.x;
    const float* src = (r < HALF) ? (zi + (size_t)r * D) : (zj + (size_t)(r - HALF) * D);
    float x = src[threadIdx.x];
    float s = x * x;
    #pragma unroll
    for (int o = 16; o > 0; o >>= 1) s += __shfl_xor_sync(0xffffffffu, s, o);
    __shared__ float ws[8];
    __shared__ float bc;
    if ((threadIdx.x & 31) == 0) ws[threadIdx.x >> 5] = s;
    __syncthreads();
    if (threadIdx.x == 0) {
        float t = 0.f;
        #pragma unroll
        for (int w = 0; w < 8; w++) t += ws[w];
        bc = rsqrtf(t) * 0.70710678118654752440f;   // * sqrt(1/TEMPERATURE)
    }
    __syncthreads();
    g_f[(size_t)r * D + threadIdx.x] = x * bc;
}

// ---------------- kernel 2: C = f * f^T (symmetric; upper-tri blocks only) ----------------
// 128x128 tile, BK=16, 256 threads, 8x8 per thread
__global__ void __launch_bounds__(256) k_gemm() {
    const int bi = blockIdx.y;     // row tile
    const int bj = blockIdx.x;     // col tile
    if (bi > bj) return;           // symmetric: compute upper triangle only

    __shared__ float As[16][128];
    __shared__ float Bs[16][128];
    const int tid = threadIdx.x;
    const int tr = tid >> 4;       // 0..15
    const int tc = tid & 15;       // 0..15
    const int i0 = bi * 128;
    const int j0 = bj * 128;

    float acc[8][8];
    #pragma unroll
    for (int u = 0; u < 8; u++)
        #pragma unroll
        for (int w = 0; w < 8; w++) acc[u][w] = 0.f;

    for (int k0 = 0; k0 < D; k0 += 16) {
        #pragma unroll
        for (int l = 0; l < 2; l++) {
            int lin = tid + l * 256;        // 0..511
            int row = lin >> 2;             // 0..127
            int c4  = lin & 3;              // 0..3
            float4 va = *(const float4*)&g_f[(size_t)(i0 + row) * D + k0 + c4 * 4];
            As[c4 * 4 + 0][row] = va.x;
            As[c4 * 4 + 1][row] = va.y;
            As[c4 * 4 + 2][row] = va.z;
            As[c4 * 4 + 3][row] = va.w;
            float4 vb = *(const float4*)&g_f[(size_t)(j0 + row) * D + k0 + c4 * 4];
            Bs[c4 * 4 + 0][row] = vb.x;
            Bs[c4 * 4 + 1][row] = vb.y;
            Bs[c4 * 4 + 2][row] = vb.z;
            Bs[c4 * 4 + 3][row] = vb.w;
        }
        __syncthreads();
        #pragma unroll
        for (int k = 0; k < 16; k++) {
            float a[8], b[8];
            float4 a0 = *(const float4*)&As[k][tr * 8];
            float4 a1 = *(const float4*)&As[k][tr * 8 + 4];
            float4 b0 = *(const float4*)&Bs[k][tc * 8];
            float4 b1 = *(const float4*)&Bs[k][tc * 8 + 4];
            a[0]=a0.x; a[1]=a0.y; a[2]=a0.z; a[3]=a0.w;
            a[4]=a1.x; a[5]=a1.y; a[6]=a1.z; a[7]=a1.w;
            b[0]=b0.x; b[1]=b0.y; b[2]=b0.z; b[3]=b0.w;
            b[4]=b1.x; b[5]=b1.y; b[6]=b1.z; b[7]=b1.w;
            #pragma unroll
            for (int u = 0; u < 8; u++)
                #pragma unroll
                for (int w = 0; w < 8; w++) acc[u][w] = fmaf(a[u], b[w], acc[u][w]);
        }
        __syncthreads();
    }
    // store (i,j) block
    #pragma unroll
    for (int u = 0; u < 8; u++) {
        size_t off = (size_t)(i0 + tr * 8 + u) * N + j0 + tc * 8;
        *(float4*)&g_logits[off]     = make_float4(acc[u][0], acc[u][1], acc[u][2], acc[u][3]);
        *(float4*)&g_logits[off + 4] = make_float4(acc[u][4], acc[u][5], acc[u][6], acc[u][7]);
    }
    // mirror store (j,i) block
    if (bi != bj) {
        #pragma unroll
        for (int w = 0; w < 8; w++) {
            size_t off = (size_t)(j0 + tc * 8 + w) * N + i0 + tr * 8;
            *(float4*)&g_logits[off]     = make_float4(acc[0][w], acc[1][w], acc[2][w], acc[3][w]);
            *(float4*)&g_logits[off + 4] = make_float4(acc[4][w], acc[5][w], acc[6][w], acc[7][w]);
        }
    }
}

// ---------------- kernel 3: per-row sort + suffix-sum + logs ----------------
__device__ __forceinline__ float4 load_label(int k, const float* __restrict__ pi,
                                             const float* __restrict__ pj) {
    const float* p = (k < HALF) ? (pi + (size_t)k * 4) : (pj + (size_t)(k - HALF) * 4);
    return __ldg((const float4*)p);
}

// -- register-phase bitonic helpers --
// warp w owns elements [w*128, w*128+128); lane l slot q holds element t = w*128 + 32*q + l
__device__ __forceinline__ void cx(unsigned &a, unsigned &b, bool asc) {
    unsigned mn = min(a, b), mx = max(a, b);
    a = asc ? mn : mx;
    b = asc ? mx : mn;
}
__device__ __forceinline__ void shflstep(unsigned r[4], int base, int l, int sz, int st) {
    #pragma unroll
    for (int q = 0; q < 4; q++) {
        int t = base + 32 * q + l;
        unsigned p = __shfl_xor_sync(0xffffffffu, r[q], st);
        bool asc = ((t & sz) == 0);
        bool lower = ((l & st) == 0);
        unsigned mn = min(r[q], p), mx = max(r[q], p);
        r[q] = (asc == lower) ? mn : mx;
    }
}
__device__ __forceinline__ void st64step(unsigned r[4], int base, int l, int sz) {
    cx(r[0], r[2], ((base + l) & sz) == 0);
    cx(r[1], r[3], ((base + 32 + l) & sz) == 0);
}
__device__ __forceinline__ void st32step(unsigned r[4], int base, int l, int sz) {
    cx(r[0], r[1], ((base + l) & sz) == 0);
    cx(r[2], r[3], ((base + 64 + l) & sz) == 0);
}
__device__ __forceinline__ void tailphase(unsigned r[4], int base, int l, int sz) {
    st64step(r, base, l, sz);
    st32step(r, base, l, sz);
    #pragma unroll
    for (int st = 16; st >= 1; st >>= 1) shflstep(r, base, l, sz, st);
}
__device__ __forceinline__ void sort128(unsigned r[4], int base, int l) {
    #pragma unroll
    for (int sz = 2; sz <= 32; sz <<= 1)
        #pragma unroll
        for (int st = 16; st >= 1; st >>= 1)
            if (st <= (sz >> 1)) shflstep(r, base, l, sz, st);
    // sz = 64
    st32step(r, base, l, 64);
    #pragma unroll
    for (int st = 16; st >= 1; st >>= 1) shflstep(r, base, l, 64, st);
    // sz = 128
    st64step(r, base, l, 128);
    st32step(r, base, l, 128);
    #pragma unroll
    for (int st = 16; st >= 1; st >>= 1) shflstep(r, base, l, 128, st);
}

__global__ void __launch_bounds__(1024) k_row(const float* __restrict__ pi,
                                              const float* __restrict__ pj) {
    __shared__ unsigned kv[N];     // (key20 << 12) | idx12
    __shared__ float    ev[N];     // exp(logit - m), 0 at diagonal
    __shared__ float redA[32];
    __shared__ float redB[32];
    __shared__ float bcast[3];     // [0]=rowmax, [1]=rowsum, [2]=diag logit

    const int i = blockIdx.x;
    const int tid = threadIdx.x;
    const int lane = tid & 31;
    const int warp = tid >> 5;
    const int base = warp * 128;

    // load 4 logits for this row
    float4 v = *(const float4*)&g_logits[(size_t)i * N + tid * 4];
    float lmax = fmaxf(fmaxf(v.x, v.y), fmaxf(v.z, v.w));
    float lsum = (v.x + v.y) + (v.z + v.w);
    #pragma unroll
    for (int o = 16; o > 0; o >>= 1) {
        lmax = fmaxf(lmax, __shfl_xor_sync(0xffffffffu, lmax, o));
        lsum += __shfl_xor_sync(0xffffffffu, lsum, o);
    }
    if (lane == 0) { redA[warp] = lmax; redB[warp] = lsum; }
    __syncthreads();
    if (warp == 0) {
        float a = redA[lane];
        float b = redB[lane];
        #pragma unroll
        for (int o = 16; o > 0; o >>= 1) {
            a = fmaxf(a, __shfl_xor_sync(0xffffffffu, a, o));
            b += __shfl_xor_sync(0xffffffffu, b, o);
        }
        if (lane == 0) { bcast[0] = a; bcast[1] = b; }
    }
    __syncthreads();
    const float m = bcast[0];
    const float sumAll = bcast[1];

    float4 li = load_label(i, pi, pj);
    float lg[4] = {v.x, v.y, v.z, v.w};
    #pragma unroll
    for (int q = 0; q < 4; q++) {
        int k = tid * 4 + q;
        if (k == i) {
            bcast[2] = lg[q];             // diagonal logit
            kv[k] = 0xffffffffu;          // guaranteed max: sorts last
            ev[k] = 0.f;                  // contributes 0 to suffix sums
        } else {
            float4 lk = load_label(k, pi, pj);
            float key = fabsf(li.x - lk.x) + fabsf(li.y - lk.y) +
                        fabsf(li.z - lk.z) + fabsf(li.w - lk.w);
            unsigned ki = (unsigned)(key * 262144.0f);       // key in [0,4) -> 20 bits
            ki = min(ki, 1048574u);                          // keep below diag sentinel
            kv[k] = (ki << 12) | (unsigned)k;
            ev[k] = __expf(lg[q] - m);
        }
    }
    __syncthreads();

    // ---- hybrid bitonic sort: smem strides >=128, register strides <=64 ----
    {
        unsigned r[4];
        #pragma unroll
        for (int q = 0; q < 4; q++) r[q] = kv[base + 32 * q + lane];
        sort128(r, base, lane);
        #pragma unroll
        for (int q = 0; q < 4; q++) kv[base + 32 * q + lane] = r[q];
        __syncthreads();
    }
    for (int sz = 256; sz <= N; sz <<= 1) {
        for (int st = sz >> 1; st >= 128; st >>= 1) {
            #pragma unroll
            for (int it = 0; it < 2; it++) {
                int idx = tid + it * 1024;                       // 0..2047
                int t = ((idx & ~(st - 1)) << 1) | (idx & (st - 1));
                int p = t | st;
                unsigned a = kv[t], b = kv[p];
                bool asc = ((t & sz) == 0);
                unsigned mn = min(a, b), mx = max(a, b);
                kv[t] = asc ? mn : mx;
                kv[p] = asc ? mx : mn;
            }
            __syncthreads();
        }
        unsigned r[4];
        #pragma unroll
        for (int q = 0; q < 4; q++) r[q] = kv[base + 32 * q + lane];
        tailphase(r, base, lane, sz);
        #pragma unroll
        for (int q = 0; q < 4; q++) kv[base + 32 * q + lane] = r[q];
        __syncthreads();
    }

    // ---- gather exp values in sorted order, suffix-sum, sum of logs ----
    uint4 sw = *(const uint4*)&kv[tid * 4];
    float v0 = ev[sw.x & 0xfffu];
    float v1 = ev[sw.y & 0xfffu];
    float v2 = ev[sw.z & 0xfffu];
    float v3 = ev[sw.w & 0xfffu];
    float s3 = v3;
    float s2 = v2 + s3;
    float s1 = v1 + s2;
    float s0 = v0 + s1;
    float tot = s0;

    // reverse (suffix) inclusive scan across lanes
    float inc = tot;
    #pragma unroll
    for (int o = 1; o < 32; o <<= 1) {
        float y = __shfl_down_sync(0xffffffffu, inc, o);
        if (lane + o < 32) inc += y;
    }
    if (lane == 0) redA[warp] = inc;
    __syncthreads();
    if (warp == 0) {
        float x = redA[lane];
        float i2 = x;
        #pragma unroll
        for (int o = 1; o < 32; o <<= 1) {
            float y = __shfl_down_sync(0xffffffffu, i2, o);
            if (lane + o < 32) i2 += y;
        }
        redB[lane] = i2 - x;          // exclusive suffix over warps > lane
    }
    __syncthreads();
    float excl = (inc - tot) + redB[warp];   // sum over threads with larger tid

    float S0 = s0 + excl;
    float S1 = s1 + excl;
    float S2 = s2 + excl;
    float S3 = s3 + excl;
    float lp = __logf(S0 + EPS) + __logf(S1 + EPS) + __logf(S2 + EPS);
    if (tid * 4 + 3 < N - 1) lp += __logf(S3 + EPS);   // exclude sorted-last (diag)

    // block-sum lp
    #pragma unroll
    for (int o = 16; o > 0; o >>= 1) lp += __shfl_xor_sync(0xffffffffu, lp, o);
    if (lane == 0) redA[warp] = lp;
    __syncthreads();
    if (warp == 0) {
        float x = redA[lane];
        #pragma unroll
        for (int o = 16; o > 0; o >>= 1) x += __shfl_xor_sync(0xffffffffu, x, o);
        if (lane == 0) {
            float diag = bcast[2];
            float sumlogit = (sumAll - (float)N * m) - (diag - m);
            g_part[i] = sumlogit - x;
        }
    }
}

// ---------------- kernel 4: deterministic final reduce ----------------
__global__ void __launch_bounds__(1024) k_final(float* __restrict__ out) {
    const int tid = threadIdx.x;
    const int lane = tid & 31;
    const int warp = tid >> 5;
    float4 p = *(const float4*)&g_part[tid * 4];
    float s = (p.x + p.y) + (p.z + p.w);
    #pragma unroll
    for (int o = 16; o > 0; o >>= 1) s += __shfl_xor_sync(0xffffffffu, s, o);
    __shared__ float ws[32];
    if (lane == 0) ws[warp] = s;
    __syncthreads();
    if (warp == 0) {
        float x = ws[lane];
        #pragma unroll
        for (int o = 16; o > 0; o >>= 1) x += __shfl_xor_sync(0xffffffffu, x, o);
        if (lane == 0) out[0] = -x / ((float)N * (float)(N - 1));
    }
}

// ---------------- entry ----------------
extern "C" void kernel_launch(void* const* d_in, const int* in_sizes, int n_in,
                              void* d_out, int out_size) {
    const float* zi = (const float*)d_in[0];
    const float* zj = (const float*)d_in[1];
    const float* pi = (const float*)d_in[2];
    const float* pj = (const float*)d_in[3];
    (void)in_sizes; (void)n_in; (void)out_size;

    k_norm<<<N, 256>>>(zi, zj);
    k_gemm<<<dim3(N / 128, N / 128), 256>>>();
    k_row<<<N, 1024>>>(pi, pj);
    k_final<<<1, 1024>>>((float*)d_out);
}

// round 9
// speedup vs baseline: 3.1027x; 1.1611x over previous
#include <cuda_runtime.h>
#include <cuda_bf16.h>
#include <cstdint>

#define N 4096
#define D 256
#define HALF 2048
#define EPS 1e-8f
#define NT 32                      // 128-wide tiles per dim
#define LDU 512                    // g_u row stride: [hi(256) | lo(256)]

// ---------------- scratch (device globals; allocation-free) ----------------
__device__ __nv_bfloat16 g_u[(size_t)N * LDU];  // 4 MB augmented [hi|lo]
__device__ float g_logits[(size_t)N * N];       // 64 MB
__device__ float g_part[N];

// ---------------- PTX helpers ----------------
__device__ __forceinline__ uint32_t smem_u32(const void* p) {
    uint32_t a;
    asm("{ .reg .u64 t; cvta.to.shared.u64 t, %1; cvt.u32.u64 %0, t; }" : "=r"(a) : "l"(p));
    return a;
}
__device__ __forceinline__ void ldsm4(uint32_t& r0, uint32_t& r1, uint32_t& r2, uint32_t& r3,
                                      uint32_t addr) {
    asm volatile("ldmatrix.sync.aligned.m8n8.x4.shared.b16 {%0,%1,%2,%3}, [%4];"
                 : "=r"(r0), "=r"(r1), "=r"(r2), "=r"(r3) : "r"(addr));
}
__device__ __forceinline__ void mma16816(float c[4], uint32_t a0, uint32_t a1, uint32_t a2,
                                         uint32_t a3, uint32_t b0, uint32_t b1) {
    asm volatile(
        "mma.sync.aligned.m16n8k16.row.col.f32.bf16.bf16.f32 "
        "{%0,%1,%2,%3}, {%4,%5,%6,%7}, {%8,%9}, {%0,%1,%2,%3};"
        : "+f"(c[0]), "+f"(c[1]), "+f"(c[2]), "+f"(c[3])
        : "r"(a0), "r"(a1), "r"(a2), "r"(a3), "r"(b0), "r"(b1));
}

// ---------------- kernel 1: normalize + bf16 hi/lo split (folds 1/T) ----------------
__global__ void k_norm(const float* __restrict__ zi, const float* __restrict__ zj) {
    int r = blockIdx.x;
    const float* src = (r < HALF) ? (zi + (size_t)r * D) : (zj + (size_t)(r - HALF) * D);
    float x = src[threadIdx.x];
    float s = x * x;
    #pragma unroll
    for (int o = 16; o > 0; o >>= 1) s += __shfl_xor_sync(0xffffffffu, s, o);
    __shared__ float ws[8];
    __shared__ float bc;
    if ((threadIdx.x & 31) == 0) ws[threadIdx.x >> 5] = s;
    __syncthreads();
    if (threadIdx.x == 0) {
        float t = 0.f;
        #pragma unroll
        for (int w = 0; w < 8; w++) t += ws[w];
        bc = rsqrtf(t) * 0.70710678118654752440f;   // * sqrt(1/TEMPERATURE)
    }
    __syncthreads();
    float v = x * bc;
    __nv_bfloat16 hi = __float2bfloat16(v);
    __nv_bfloat16 lo = __float2bfloat16(v - __bfloat162float(hi));
    g_u[(size_t)r * LDU + threadIdx.x]       = hi;
    g_u[(size_t)r * LDU + 256 + threadIdx.x] = lo;
}

// ---------------- kernel 2: mma.sync bf16 split GEMM, upper-tri tiles ----------------
// 528 blocks, 256 threads (8 warps 2x4), 128x128 tile, warp tile 64x32.
// 3 passes (hi*hi, hi*lo, lo*hi) x 4 chunks of BK=64 accumulate in f32 regs.
// smem: As[128][72] bf16 @0 (18432B), Bs[128][72] bf16 @18432  -> 36864B
// epilogue reuse: smemN[128][68] f32 @0 (34816B), smemT[64][132] f32 @34816 (33792B) -> 68608B
__global__ void __launch_bounds__(256) k_gemm_mma() {
    extern __shared__ char dsm[];
    const uint32_t sbase = smem_u32(dsm);
    __nv_bfloat16* As = (__nv_bfloat16*)dsm;             // stride 72
    __nv_bfloat16* Bs = (__nv_bfloat16*)(dsm + 18432);   // stride 72
    float* smemN = (float*)dsm;                          // [128][68]
    float* smemT = (float*)(dsm + 34816);                // [64][132]

    const int tid = threadIdx.x;
    const int wid = tid >> 5;
    const int lane = tid & 31;
    const int wr = wid >> 2;        // 0..1  (64-row band)
    const int wc = wid & 3;         // 0..3  (32-col band)

    // decode upper-tri tile (bi <= bj)
    int rem = blockIdx.x;
    int bi = 0;
    while (rem >= NT - bi) { rem -= NT - bi; bi++; }
    const int bj = bi + rem;
    const int i0 = bi * 128, j0 = bj * 128;

    float cc[4][4][4];
    #pragma unroll
    for (int am = 0; am < 4; am++)
        #pragma unroll
        for (int bn = 0; bn < 4; bn++)
            #pragma unroll
            for (int q = 0; q < 4; q++) cc[am][bn][q] = 0.f;

    // per-thread load indices (4 x uint4 per tile)
    const int ldr = tid >> 3;         // 0..31 base row
    const int ldc8 = (tid & 7) * 8;   // 0..56

    // ldmatrix source addresses (byte offsets in smem)
    const uint32_t a_ls_base = sbase + (uint32_t)(wr * 64 + (lane & 15)) * 144u + (uint32_t)(lane >> 4) * 16u;
    const int b_nrow = wc * 32 + (lane & 7) + ((lane & 16) ? 8 : 0);
    const uint32_t b_ls_base = sbase + 18432u + (uint32_t)b_nrow * 144u + ((lane & 8) ? 16u : 0u);

    #pragma unroll
    for (int pass = 0; pass < 3; pass++) {
        const int aoff = (pass == 2) ? 256 : 0;
        const int boff = (pass == 1) ? 256 : 0;
        for (int kc = 0; kc < 4; kc++) {
            const int k0 = kc * 64;
            __syncthreads();
            #pragma unroll
            for (int it = 0; it < 4; it++) {
                int r = ldr + it * 32;
                uint4 va = *(const uint4*)&g_u[(size_t)(i0 + r) * LDU + aoff + k0 + ldc8];
                *(uint4*)&As[r * 72 + ldc8] = va;
                uint4 vb = *(const uint4*)&g_u[(size_t)(j0 + r) * LDU + boff + k0 + ldc8];
                *(uint4*)&Bs[r * 72 + ldc8] = vb;
            }
            __syncthreads();
            #pragma unroll
            for (int kk = 0; kk < 64; kk += 16) {
                uint32_t af[4][4];
                #pragma unroll
                for (int am = 0; am < 4; am++)
                    ldsm4(af[am][0], af[am][1], af[am][2], af[am][3],
                          a_ls_base + (uint32_t)(am * 16) * 144u + (uint32_t)kk * 2u);
                uint32_t bf[2][4];
                #pragma unroll
                for (int g = 0; g < 2; g++)
                    ldsm4(bf[g][0], bf[g][1], bf[g][2], bf[g][3],
                          b_ls_base + (uint32_t)(g * 16) * 144u + (uint32_t)kk * 2u);
                #pragma unroll
                for (int am = 0; am < 4; am++)
                    #pragma unroll
                    for (int bn = 0; bn < 4; bn++)
                        mma16816(cc[am][bn], af[am][0], af[am][1], af[am][2], af[am][3],
                                 bf[bn >> 1][(bn & 1) * 2], bf[bn >> 1][(bn & 1) * 2 + 1]);
            }
        }
    }

    // ---- epilogue: two 64-col halves via dual-orientation smem staging ----
    for (int h = 0; h < 2; h++) {
        __syncthreads();
        if ((wc >> 1) == h) {
            #pragma unroll
            for (int am = 0; am < 4; am++) {
                int r = wr * 64 + am * 16 + (lane >> 2);
                #pragma unroll
                for (int bn = 0; bn < 4; bn++) {
                    int c = (wc & 1) * 32 + bn * 8 + (lane & 3) * 2;
                    smemN[r * 68 + c]           = cc[am][bn][0];
                    smemN[r * 68 + c + 1]       = cc[am][bn][1];
                    smemN[(r + 8) * 68 + c]     = cc[am][bn][2];
                    smemN[(r + 8) * 68 + c + 1] = cc[am][bn][3];
                    smemT[c * 132 + r]            = cc[am][bn][0];
                    smemT[(c + 1) * 132 + r]      = cc[am][bn][1];
                    smemT[c * 132 + r + 8]        = cc[am][bn][2];
                    smemT[(c + 1) * 132 + r + 8]  = cc[am][bn][3];
                }
            }
        }
        __syncthreads();
        // normal-orientation store: rows i0..i0+127, cols j0+h*64..+63
        #pragma unroll
        for (int e = 0; e < 8; e++) {
            int idx = e * 256 + tid;            // 0..2047
            int r = idx >> 4;
            int c4 = (idx & 15) * 4;
            float4 v = *(const float4*)&smemN[r * 68 + c4];
            *(float4*)&g_logits[(size_t)(i0 + r) * N + j0 + h * 64 + c4] = v;
        }
        // mirror store: rows j0+h*64..+63, cols i0..i0+127
        if (bi != bj) {
            #pragma unroll
            for (int e = 0; e < 8; e++) {
                int idx = e * 256 + tid;        // 0..2047
                int c = idx >> 5;               // 0..63
                int r4 = (idx & 31) * 4;
                float4 v = *(const float4*)&smemT[c * 132 + r4];
                *(float4*)&g_logits[(size_t)(j0 + h * 64 + c) * N + i0 + r4] = v;
            }
        }
    }
}

// ---------------- kernel 3: per-row sort + suffix-sum + logs ----------------
__device__ __forceinline__ float4 load_label(int k, const float* __restrict__ pi,
                                             const float* __restrict__ pj) {
    const float* p = (k < HALF) ? (pi + (size_t)k * 4) : (pj + (size_t)(k - HALF) * 4);
    return __ldg((const float4*)p);
}

// -- register-phase bitonic helpers --
__device__ __forceinline__ void cx(unsigned &a, unsigned &b, bool asc) {
    unsigned mn = min(a, b), mx = max(a, b);
    a = asc ? mn : mx;
    b = asc ? mx : mn;
}
__device__ __forceinline__ void shflstep(unsigned r[4], int base, int l, int sz, int st) {
    #pragma unroll
    for (int q = 0; q < 4; q++) {
        int t = base + 32 * q + l;
        unsigned p = __shfl_xor_sync(0xffffffffu, r[q], st);
        bool asc = ((t & sz) == 0);
        bool lower = ((l & st) == 0);
        unsigned mn = min(r[q], p), mx = max(r[q], p);
        r[q] = (asc == lower) ? mn : mx;
    }
}
__device__ __forceinline__ void st64step(unsigned r[4], int base, int l, int sz) {
    cx(r[0], r[2], ((base + l) & sz) == 0);
    cx(r[1], r[3], ((base + 32 + l) & sz) == 0);
}
__device__ __forceinline__ void st32step(unsigned r[4], int base, int l, int sz) {
    cx(r[0], r[1], ((base + l) & sz) == 0);
    cx(r[2], r[3], ((base + 64 + l) & sz) == 0);
}
__device__ __forceinline__ void tailphase(unsigned r[4], int base, int l, int sz) {
    st64step(r, base, l, sz);
    st32step(r, base, l, sz);
    #pragma unroll
    for (int st = 16; st >= 1; st >>= 1) shflstep(r, base, l, sz, st);
}
__device__ __forceinline__ void sort128(unsigned r[4], int base, int l) {
    #pragma unroll
    for (int sz = 2; sz <= 32; sz <<= 1)
        #pragma unroll
        for (int st = 16; st >= 1; st >>= 1)
            if (st <= (sz >> 1)) shflstep(r, base, l, sz, st);
    st32step(r, base, l, 64);
    #pragma unroll
    for (int st = 16; st >= 1; st >>= 1) shflstep(r, base, l, 64, st);
    st64step(r, base, l, 128);
    st32step(r, base, l, 128);
    #pragma unroll
    for (int st = 16; st >= 1; st >>= 1) shflstep(r, base, l, 128, st);
}

__global__ void __launch_bounds__(1024) k_row(const float* __restrict__ pi,
                                              const float* __restrict__ pj) {
    __shared__ unsigned kv[N];
    __shared__ float    ev[N];
    __shared__ float redA[32];
    __shared__ float redB[32];
    __shared__ float bcast[3];

    const int i = blockIdx.x;
    const int tid = threadIdx.x;
    const int lane = tid & 31;
    const int warp = tid >> 5;
    const int base = warp * 128;

    float4 v = *(const float4*)&g_logits[(size_t)i * N + tid * 4];
    float lmax = fmaxf(fmaxf(v.x, v.y), fmaxf(v.z, v.w));
    float lsum = (v.x + v.y) + (v.z + v.w);
    #pragma unroll
    for (int o = 16; o > 0; o >>= 1) {
        lmax = fmaxf(lmax, __shfl_xor_sync(0xffffffffu, lmax, o));
        lsum += __shfl_xor_sync(0xffffffffu, lsum, o);
    }
    if (lane == 0) { redA[warp] = lmax; redB[warp] = lsum; }
    __syncthreads();
    if (warp == 0) {
        float a = redA[lane];
        float b = redB[lane];
        #pragma unroll
        for (int o = 16; o > 0; o >>= 1) {
            a = fmaxf(a, __shfl_xor_sync(0xffffffffu, a, o));
            b += __shfl_xor_sync(0xffffffffu, b, o);
        }
        if (lane == 0) { bcast[0] = a; bcast[1] = b; }
    }
    __syncthreads();
    const float m = bcast[0];
    const float sumAll = bcast[1];

    float4 li = load_label(i, pi, pj);
    float lg[4] = {v.x, v.y, v.z, v.w};
    #pragma unroll
    for (int q = 0; q < 4; q++) {
        int k = tid * 4 + q;
        if (k == i) {
            bcast[2] = lg[q];
            kv[k] = 0xffffffffu;
            ev[k] = 0.f;
        } else {
            float4 lk = load_label(k, pi, pj);
            float key = fabsf(li.x - lk.x) + fabsf(li.y - lk.y) +
                        fabsf(li.z - lk.z) + fabsf(li.w - lk.w);
            unsigned ki = (unsigned)(key * 262144.0f);
            ki = min(ki, 1048574u);
            kv[k] = (ki << 12) | (unsigned)k;
            ev[k] = __expf(lg[q] - m);
        }
    }
    __syncthreads();

    {
        unsigned r[4];
        #pragma unroll
        for (int q = 0; q < 4; q++) r[q] = kv[base + 32 * q + lane];
        sort128(r, base, lane);
        #pragma unroll
        for (int q = 0; q < 4; q++) kv[base + 32 * q + lane] = r[q];
        __syncthreads();
    }
    for (int sz = 256; sz <= N; sz <<= 1) {
        for (int st = sz >> 1; st >= 128; st >>= 1) {
            #pragma unroll
            for (int it = 0; it < 2; it++) {
                int idx = tid + it * 1024;
                int t = ((idx & ~(st - 1)) << 1) | (idx & (st - 1));
                int p = t | st;
                unsigned a = kv[t], b = kv[p];
                bool asc = ((t & sz) == 0);
                unsigned mn = min(a, b), mx = max(a, b);
                kv[t] = asc ? mn : mx;
                kv[p] = asc ? mx : mn;
            }
            __syncthreads();
        }
        unsigned r[4];
        #pragma unroll
        for (int q = 0; q < 4; q++) r[q] = kv[base + 32 * q + lane];
        tailphase(r, base, lane, sz);
        #pragma unroll
        for (int q = 0; q < 4; q++) kv[base + 32 * q + lane] = r[q];
        __syncthreads();
    }

    uint4 sw = *(const uint4*)&kv[tid * 4];
    float v0 = ev[sw.x & 0xfffu];
    float v1 = ev[sw.y & 0xfffu];
    float v2 = ev[sw.z & 0xfffu];
    float v3 = ev[sw.w & 0xfffu];
    float s3 = v3;
    float s2 = v2 + s3;
    float s1 = v1 + s2;
    float s0 = v0 + s1;
    float tot = s0;

    float inc = tot;
    #pragma unroll
    for (int o = 1; o < 32; o <<= 1) {
        float y = __shfl_down_sync(0xffffffffu, inc, o);
        if (lane + o < 32) inc += y;
    }
    if (lane == 0) redA[warp] = inc;
    __syncthreads();
    if (warp == 0) {
        float x = redA[lane];
        float i2 = x;
        #pragma unroll
        for (int o = 1; o < 32; o <<= 1) {
            float y = __shfl_down_sync(0xffffffffu, i2, o);
            if (lane + o < 32) i2 += y;
        }
        redB[lane] = i2 - x;
    }
    __syncthreads();
    float excl = (inc - tot) + redB[warp];

    float S0 = s0 + excl;
    float S1 = s1 + excl;
    float S2 = s2 + excl;
    float S3 = s3 + excl;
    float lp = __logf(S0 + EPS) + __logf(S1 + EPS) + __logf(S2 + EPS);
    if (tid * 4 + 3 < N - 1) lp += __logf(S3 + EPS);

    #pragma unroll
    for (int o = 16; o > 0; o >>= 1) lp += __shfl_xor_sync(0xffffffffu, lp, o);
    if (lane == 0) redA[warp] = lp;
    __syncthreads();
    if (warp == 0) {
        float x = redA[lane];
        #pragma unroll
        for (int o = 16; o > 0; o >>= 1) x += __shfl_xor_sync(0xffffffffu, x, o);
        if (lane == 0) {
            float diag = bcast[2];
            float sumlogit = (sumAll - (float)N * m) - (diag - m);
            g_part[i] = sumlogit - x;
        }
    }
}

// ---------------- kernel 4: deterministic final reduce ----------------
__global__ void __launch_bounds__(1024) k_final(float* __restrict__ out) {
    const int tid = threadIdx.x;
    const int lane = tid & 31;
    const int warp = tid >> 5;
    float4 p = *(const float4*)&g_part[tid * 4];
    float s = (p.x + p.y) + (p.z + p.w);
    #pragma unroll
    for (int o = 16; o > 0; o >>= 1) s += __shfl_xor_sync(0xffffffffu, s, o);
    __shared__ float ws[32];
    if (lane == 0) ws[warp] = s;
    __syncthreads();
    if (warp == 0) {
        float x = ws[lane];
        #pragma unroll
        for (int o = 16; o > 0; o >>= 1) x += __shfl_xor_sync(0xffffffffu, x, o);
        if (lane == 0) out[0] = -x / ((float)N * (float)(N - 1));
    }
}

// ---------------- entry ----------------
extern "C" void kernel_launch(void* const* d_in, const int* in_sizes, int n_in,
                              void* d_out, int out_size) {
    const float* zi = (const float*)d_in[0];
    const float* zj = (const float*)d_in[1];
    const float* pi = (const float*)d_in[2];
    const float* pj = (const float*)d_in[3];
    (void)in_sizes; (void)n_in; (void)out_size;

    cudaFuncSetAttribute(k_gemm_mma, cudaFuncAttributeMaxDynamicSharedMemorySize, 68608);

    k_norm<<<N, 256>>>(zi, zj);
    k_gemm_mma<<<NT * (NT + 1) / 2, 256, 68608>>>();
    k_row<<<N, 1024>>>(pi, pj);
    k_final<<<1, 1024>>>((float*)d_out);
}

// round 12
// speedup vs baseline: 4.2785x; 1.3790x over previous
#include <cuda_runtime.h>
#include <cuda_bf16.h>
#include <cstdint>

#define N 4096
#define D 256
#define HALF 2048
#define EPS 1e-8f
#define NT 32                      // 128-wide tiles per dim
#define LDU 512                    // g_u row stride: [hi(256) | lo(256)]

// ---------------- scratch (device globals; allocation-free) ----------------
__device__ __nv_bfloat16 g_u[(size_t)N * LDU];  // 4 MB augmented [hi|lo]
__device__ float g_logits[(size_t)N * N];       // 64 MB
__device__ float g_part[N];

// ---------------- PTX helpers ----------------
__device__ __forceinline__ uint32_t smem_u32(const void* p) {
    uint32_t a;
    asm("{ .reg .u64 t; cvta.to.shared.u64 t, %1; cvt.u32.u64 %0, t; }" : "=r"(a) : "l"(p));
    return a;
}
__device__ __forceinline__ void ldsm4(uint32_t& r0, uint32_t& r1, uint32_t& r2, uint32_t& r3,
                                      uint32_t addr) {
    asm volatile("ldmatrix.sync.aligned.m8n8.x4.shared.b16 {%0,%1,%2,%3}, [%4];"
                 : "=r"(r0), "=r"(r1), "=r"(r2), "=r"(r3) : "r"(addr));
}
__device__ __forceinline__ void mma16816(float c[4], uint32_t a0, uint32_t a1, uint32_t a2,
                                         uint32_t a3, uint32_t b0, uint32_t b1) {
    asm volatile(
        "mma.sync.aligned.m16n8k16.row.col.f32.bf16.bf16.f32 "
        "{%0,%1,%2,%3}, {%4,%5,%6,%7}, {%8,%9}, {%0,%1,%2,%3};"
        : "+f"(c[0]), "+f"(c[1]), "+f"(c[2]), "+f"(c[3])
        : "r"(a0), "r"(a1), "r"(a2), "r"(a3), "r"(b0), "r"(b1));
}

// ---------------- kernel 1: normalize + bf16 hi/lo split (folds 1/T) ----------------
__global__ void k_norm(const float* __restrict__ zi, const float* __restrict__ zj) {
    int r = blockIdx.x;
    const float* src = (r < HALF) ? (zi + (size_t)r * D) : (zj + (size_t)(r - HALF) * D);
    float x = src[threadIdx.x];
    float s = x * x;
    #pragma unroll
    for (int o = 16; o > 0; o >>= 1) s += __shfl_xor_sync(0xffffffffu, s, o);
    __shared__ float ws[8];
    __shared__ float bc;
    if ((threadIdx.x & 31) == 0) ws[threadIdx.x >> 5] = s;
    __syncthreads();
    if (threadIdx.x == 0) {
        float t = 0.f;
        #pragma unroll
        for (int w = 0; w < 8; w++) t += ws[w];
        bc = rsqrtf(t) * 0.70710678118654752440f;   // * sqrt(1/TEMPERATURE)
    }
    __syncthreads();
    float v = x * bc;
    __nv_bfloat16 hi = __float2bfloat16(v);
    __nv_bfloat16 lo = __float2bfloat16(v - __bfloat162float(hi));
    g_u[(size_t)r * LDU + threadIdx.x]       = hi;
    g_u[(size_t)r * LDU + 256 + threadIdx.x] = lo;
}

// ---------------- kernel 2: mma.sync bf16 split GEMM, upper-tri tiles ----------------
// (unchanged from R9 passing build)
__global__ void __launch_bounds__(256) k_gemm_mma() {
    extern __shared__ char dsm[];
    const uint32_t sbase = smem_u32(dsm);
    __nv_bfloat16* As = (__nv_bfloat16*)dsm;             // stride 72
    __nv_bfloat16* Bs = (__nv_bfloat16*)(dsm + 18432);   // stride 72
    float* smemN = (float*)dsm;                          // [128][68]
    float* smemT = (float*)(dsm + 34816);                // [64][132]

    const int tid = threadIdx.x;
    const int wid = tid >> 5;
    const int lane = tid & 31;
    const int wr = wid >> 2;
    const int wc = wid & 3;

    int rem = blockIdx.x;
    int bi = 0;
    while (rem >= NT - bi) { rem -= NT - bi; bi++; }
    const int bj = bi + rem;
    const int i0 = bi * 128, j0 = bj * 128;

    float cc[4][4][4];
    #pragma unroll
    for (int am = 0; am < 4; am++)
        #pragma unroll
        for (int bn = 0; bn < 4; bn++)
            #pragma unroll
            for (int q = 0; q < 4; q++) cc[am][bn][q] = 0.f;

    const int ldr = tid >> 3;
    const int ldc8 = (tid & 7) * 8;

    const uint32_t a_ls_base = sbase + (uint32_t)(wr * 64 + (lane & 15)) * 144u + (uint32_t)(lane >> 4) * 16u;
    const int b_nrow = wc * 32 + (lane & 7) + ((lane & 16) ? 8 : 0);
    const uint32_t b_ls_base = sbase + 18432u + (uint32_t)b_nrow * 144u + ((lane & 8) ? 16u : 0u);

    #pragma unroll
    for (int pass = 0; pass < 3; pass++) {
        const int aoff = (pass == 2) ? 256 : 0;
        const int boff = (pass == 1) ? 256 : 0;
        for (int kc = 0; kc < 4; kc++) {
            const int k0 = kc * 64;
            __syncthreads();
            #pragma unroll
            for (int it = 0; it < 4; it++) {
                int r = ldr + it * 32;
                uint4 va = *(const uint4*)&g_u[(size_t)(i0 + r) * LDU + aoff + k0 + ldc8];
                *(uint4*)&As[r * 72 + ldc8] = va;
                uint4 vb = *(const uint4*)&g_u[(size_t)(j0 + r) * LDU + boff + k0 + ldc8];
                *(uint4*)&Bs[r * 72 + ldc8] = vb;
            }
            __syncthreads();
            #pragma unroll
            for (int kk = 0; kk < 64; kk += 16) {
                uint32_t af[4][4];
                #pragma unroll
                for (int am = 0; am < 4; am++)
                    ldsm4(af[am][0], af[am][1], af[am][2], af[am][3],
                          a_ls_base + (uint32_t)(am * 16) * 144u + (uint32_t)kk * 2u);
                uint32_t bf[2][4];
                #pragma unroll
                for (int g = 0; g < 2; g++)
                    ldsm4(bf[g][0], bf[g][1], bf[g][2], bf[g][3],
                          b_ls_base + (uint32_t)(g * 16) * 144u + (uint32_t)kk * 2u);
                #pragma unroll
                for (int am = 0; am < 4; am++)
                    #pragma unroll
                    for (int bn = 0; bn < 4; bn++)
                        mma16816(cc[am][bn], af[am][0], af[am][1], af[am][2], af[am][3],
                                 bf[bn >> 1][(bn & 1) * 2], bf[bn >> 1][(bn & 1) * 2 + 1]);
            }
        }
    }

    for (int h = 0; h < 2; h++) {
        __syncthreads();
        if ((wc >> 1) == h) {
            #pragma unroll
            for (int am = 0; am < 4; am++) {
                int r = wr * 64 + am * 16 + (lane >> 2);
                #pragma unroll
                for (int bn = 0; bn < 4; bn++) {
                    int c = (wc & 1) * 32 + bn * 8 + (lane & 3) * 2;
                    smemN[r * 68 + c]           = cc[am][bn][0];
                    smemN[r * 68 + c + 1]       = cc[am][bn][1];
                    smemN[(r + 8) * 68 + c]     = cc[am][bn][2];
                    smemN[(r + 8) * 68 + c + 1] = cc[am][bn][3];
                    smemT[c * 132 + r]            = cc[am][bn][0];
                    smemT[(c + 1) * 132 + r]      = cc[am][bn][1];
                    smemT[c * 132 + r + 8]        = cc[am][bn][2];
                    smemT[(c + 1) * 132 + r + 8]  = cc[am][bn][3];
                }
            }
        }
        __syncthreads();
        #pragma unroll
        for (int e = 0; e < 8; e++) {
            int idx = e * 256 + tid;
            int r = idx >> 4;
            int c4 = (idx & 15) * 4;
            float4 v = *(const float4*)&smemN[r * 68 + c4];
            *(float4*)&g_logits[(size_t)(i0 + r) * N + j0 + h * 64 + c4] = v;
        }
        if (bi != bj) {
            #pragma unroll
            for (int e = 0; e < 8; e++) {
                int idx = e * 256 + tid;
                int c = idx >> 5;
                int r4 = (idx & 31) * 4;
                float4 v = *(const float4*)&smemT[c * 132 + r4];
                *(float4*)&g_logits[(size_t)(j0 + h * 64 + c) * N + i0 + r4] = v;
            }
        }
    }
}

// ---------------- kernel 3: per-row COUNTING SORT + suffix-sum + logs ----------------
// dynamic smem layout: kv u32[4096]@0 | ev f32[4096]@16384 | srt u32[4096]@32768 | cnt u32[4096]@49152
__device__ __forceinline__ float4 load_label(int k, const float* __restrict__ pi,
                                             const float* __restrict__ pj) {
    const float* p = (k < HALF) ? (pi + (size_t)k * 4) : (pj + (size_t)(k - HALF) * 4);
    return __ldg((const float4*)p);
}

__global__ void __launch_bounds__(1024) k_row(const float* __restrict__ pi,
                                              const float* __restrict__ pj) {
    extern __shared__ char drow[];
    unsigned* kv  = (unsigned*)drow;             // composite keys (key20|idx12)
    float*    ev  = (float*)(drow + 16384);      // exp values by original idx
    unsigned* srt = (unsigned*)(drow + 32768);   // sorted composite keys
    unsigned* cnt = (unsigned*)(drow + 49152);   // histogram -> offsets -> cursors -> ends
    __shared__ float redA[32];
    __shared__ float redB[32];
    __shared__ float bcast[3];

    const int i = blockIdx.x;
    const int tid = threadIdx.x;
    const int lane = tid & 31;
    const int warp = tid >> 5;

    // ---- row max + sum ----
    float4 v = *(const float4*)&g_logits[(size_t)i * N + tid * 4];
    float lmax = fmaxf(fmaxf(v.x, v.y), fmaxf(v.z, v.w));
    float lsum = (v.x + v.y) + (v.z + v.w);
    #pragma unroll
    for (int o = 16; o > 0; o >>= 1) {
        lmax = fmaxf(lmax, __shfl_xor_sync(0xffffffffu, lmax, o));
        lsum += __shfl_xor_sync(0xffffffffu, lsum, o);
    }
    if (lane == 0) { redA[warp] = lmax; redB[warp] = lsum; }
    __syncthreads();
    if (warp == 0) {
        float a = redA[lane];
        float b = redB[lane];
        #pragma unroll
        for (int o = 16; o > 0; o >>= 1) {
            a = fmaxf(a, __shfl_xor_sync(0xffffffffu, a, o));
            b += __shfl_xor_sync(0xffffffffu, b, o);
        }
        if (lane == 0) { bcast[0] = a; bcast[1] = b; }
    }
    __syncthreads();
    const float m = bcast[0];
    const float sumAll = bcast[1];

    // ---- build composite keys + exp values; zero histogram ----
    float4 li = load_label(i, pi, pj);
    float lg[4] = {v.x, v.y, v.z, v.w};
    unsigned myk[4];
    #pragma unroll
    for (int q = 0; q < 4; q++) {
        int k = tid * 4 + q;
        if (k == i) {
            bcast[2] = lg[q];
            myk[q] = 0xfffff000u | (unsigned)i;  // key field all-ones (> any real key),
            ev[k] = 0.f;                         // low bits = i so gather reads ev[i] = 0
        } else {
            float4 lk = load_label(k, pi, pj);
            float key = fabsf(li.x - lk.x) + fabsf(li.y - lk.y) +
                        fabsf(li.z - lk.z) + fabsf(li.w - lk.w);
            unsigned ki = (unsigned)(key * 262144.0f);
            ki = min(ki, 1048574u);
            myk[q] = (ki << 12) | (unsigned)k;
            ev[k] = __expf(lg[q] - m);
        }
        kv[k] = myk[q];
        cnt[k] = 0u;
    }
    __syncthreads();

    // ---- histogram over top-12-bit buckets ----
    #pragma unroll
    for (int q = 0; q < 4; q++) atomicAdd(&cnt[myk[q] >> 20], 1u);
    __syncthreads();

    // ---- in-place exclusive scan of cnt[4096] (4 per thread) ----
    unsigned c0 = cnt[tid * 4 + 0], c1 = cnt[tid * 4 + 1],
             c2 = cnt[tid * 4 + 2], c3 = cnt[tid * 4 + 3];
    unsigned s = c0 + c1 + c2 + c3;
    unsigned si = s;
    #pragma unroll
    for (int o = 1; o < 32; o <<= 1) {
        unsigned y = __shfl_up_sync(0xffffffffu, si, o);
        if (lane >= o) si += y;
    }
    if (lane == 31) redA[warp] = __uint_as_float(si);
    __syncthreads();
    if (warp == 0) {
        unsigned x = __float_as_uint(redA[lane]);
        unsigned xi = x;
        #pragma unroll
        for (int o = 1; o < 32; o <<= 1) {
            unsigned y = __shfl_up_sync(0xffffffffu, xi, o);
            if (lane >= o) xi += y;
        }
        redB[lane] = __uint_as_float(xi - x);   // exclusive warp base
    }
    __syncthreads();
    unsigned base = __float_as_uint(redB[warp]) + (si - s);
    cnt[tid * 4 + 0] = base;
    cnt[tid * 4 + 1] = base + c0;
    cnt[tid * 4 + 2] = base + c0 + c1;
    cnt[tid * 4 + 3] = base + c0 + c1 + c2;
    __syncthreads();

    // ---- scatter into buckets (cnt becomes per-bucket end offsets) ----
    #pragma unroll
    for (int q = 0; q < 4; q++) {
        unsigned pos = atomicAdd(&cnt[myk[q] >> 20], 1u);
        srt[pos] = myk[q];
    }
    __syncthreads();

    // ---- insertion sort within each tiny bucket (thread t: buckets 4t..4t+3) ----
    #pragma unroll
    for (int q = 0; q < 4; q++) {
        int b = tid * 4 + q;
        int st = (b == 0) ? 0 : (int)cnt[b - 1];
        int en = (int)cnt[b];
        for (int x = st + 1; x < en; x++) {
            unsigned key = srt[x];
            int y = x - 1;
            while (y >= st && srt[y] > key) { srt[y + 1] = srt[y]; y--; }
            srt[y + 1] = key;
        }
    }
    __syncthreads();

    // ---- gather exp in sorted order, suffix-sum, sum of logs ----
    uint4 sw = *(const uint4*)&srt[tid * 4];
    float v0 = ev[sw.x & 0xfffu];
    float v1 = ev[sw.y & 0xfffu];
    float v2 = ev[sw.z & 0xfffu];
    float v3 = ev[sw.w & 0xfffu];
    float s3 = v3;
    float s2 = v2 + s3;
    float s1 = v1 + s2;
    float s0 = v0 + s1;
    float tot = s0;

    float inc = tot;
    #pragma unroll
    for (int o = 1; o < 32; o <<= 1) {
        float y = __shfl_down_sync(0xffffffffu, inc, o);
        if (lane + o < 32) inc += y;
    }
    if (lane == 0) redA[warp] = inc;
    __syncthreads();
    if (warp == 0) {
        float x = redA[lane];
        float i2 = x;
        #pragma unroll
        for (int o = 1; o < 32; o <<= 1) {
            float y = __shfl_down_sync(0xffffffffu, i2, o);
            if (lane + o < 32) i2 += y;
        }
        redB[lane] = i2 - x;
    }
    __syncthreads();
    float excl = (inc - tot) + redB[warp];

    float S0 = s0 + excl;
    float S1 = s1 + excl;
    float S2 = s2 + excl;
    float S3 = s3 + excl;
    float lp = __logf(S0 + EPS) + __logf(S1 + EPS) + __logf(S2 + EPS);
    if (tid * 4 + 3 < N - 1) lp += __logf(S3 + EPS);

    #pragma unroll
    for (int o = 16; o > 0; o >>= 1) lp += __shfl_xor_sync(0xffffffffu, lp, o);
    if (lane == 0) redA[warp] = lp;
    __syncthreads();
    if (warp == 0) {
        float x = redA[lane];
        #pragma unroll
        for (int o = 16; o > 0; o >>= 1) x += __shfl_xor_sync(0xffffffffu, x, o);
        if (lane == 0) {
            float diag = bcast[2];
            float sumlogit = (sumAll - (float)N * m) - (diag - m);
            g_part[i] = sumlogit - x;
        }
    }
}

// ---------------- kernel 4: deterministic final reduce ----------------
__global__ void __launch_bounds__(1024) k_final(float* __restrict__ out) {
    const int tid = threadIdx.x;
    const int lane = tid & 31;
    const int warp = tid >> 5;
    float4 p = *(const float4*)&g_part[tid * 4];
    float s = (p.x + p.y) + (p.z + p.w);
    #pragma unroll
    for (int o = 16; o > 0; o >>= 1) s += __shfl_xor_sync(0xffffffffu, s, o);
    __shared__ float ws[32];
    if (lane == 0) ws[warp] = s;
    __syncthreads();
    if (warp == 0) {
        float x = ws[lane];
        #pragma unroll
        for (int o = 16; o > 0; o >>= 1) x += __shfl_xor_sync(0xffffffffu, x, o);
        if (lane == 0) out[0] = -x / ((float)N * (float)(N - 1));
    }
}

// ---------------- entry ----------------
extern "C" void kernel_launch(void* const* d_in, const int* in_sizes, int n_in,
                              void* d_out, int out_size) {
    const float* zi = (const float*)d_in[0];
    const float* zj = (const float*)d_in[1];
    const float* pi = (const float*)d_in[2];
    const float* pj = (const float*)d_in[3];
    (void)in_sizes; (void)n_in; (void)out_size;

    cudaFuncSetAttribute(k_gemm_mma, cudaFuncAttributeMaxDynamicSharedMemorySize, 68608);
    cudaFuncSetAttribute(k_row, cudaFuncAttributeMaxDynamicSharedMemorySize, 65536);

    k_norm<<<N, 256>>>(zi, zj);
    k_gemm_mma<<<NT * (NT + 1) / 2, 256, 68608>>>();
    k_row<<<N, 1024, 65536>>>(pi, pj);
    k_final<<<1, 1024>>>((float*)d_out);
}

// round 14
// speedup vs baseline: 4.2868x; 1.0019x over previous
#include <cuda_runtime.h>
#include <cuda_bf16.h>
#include <cstdint>

#define N 4096
#define D 256
#define HALF 2048
#define EPS 1e-8f
#define NT 32                      // 128-wide tiles per dim
#define LDU 512                    // g_u row stride: [hi(256) | lo(256)]

// ---------------- scratch (device globals; allocation-free) ----------------
__device__ __nv_bfloat16 g_u[(size_t)N * LDU];  // 4 MB augmented [hi|lo]
__device__ float g_logits[(size_t)N * N];       // 64 MB
__device__ float g_part[N];

// ---------------- PTX helpers ----------------
__device__ __forceinline__ uint32_t smem_u32(const void* p) {
    uint32_t a;
    asm("{ .reg .u64 t; cvta.to.shared.u64 t, %1; cvt.u32.u64 %0, t; }" : "=r"(a) : "l"(p));
    return a;
}
__device__ __forceinline__ void ldsm4(uint32_t& r0, uint32_t& r1, uint32_t& r2, uint32_t& r3,
                                      uint32_t addr) {
    asm volatile("ldmatrix.sync.aligned.m8n8.x4.shared.b16 {%0,%1,%2,%3}, [%4];"
                 : "=r"(r0), "=r"(r1), "=r"(r2), "=r"(r3) : "r"(addr));
}
__device__ __forceinline__ void mma16816(float c[4], uint32_t a0, uint32_t a1, uint32_t a2,
                                         uint32_t a3, uint32_t b0, uint32_t b1) {
    asm volatile(
        "mma.sync.aligned.m16n8k16.row.col.f32.bf16.bf16.f32 "
        "{%0,%1,%2,%3}, {%4,%5,%6,%7}, {%8,%9}, {%0,%1,%2,%3};"
        : "+f"(c[0]), "+f"(c[1]), "+f"(c[2]), "+f"(c[3])
        : "r"(a0), "r"(a1), "r"(a2), "r"(a3), "r"(b0), "r"(b1));
}
#define CP_ASYNC16(dst, src) \
    asm volatile("cp.async.cg.shared.global [%0], [%1], 16;" :: "r"(dst), "l"(src))
#define CP_COMMIT()  asm volatile("cp.async.commit_group;" ::: "memory")
#define CP_WAIT0()   asm volatile("cp.async.wait_group 0;" ::: "memory")

// ---------------- kernel 1: normalize + bf16 hi/lo split (folds 1/T) ----------------
__global__ void k_norm(const float* __restrict__ zi, const float* __restrict__ zj) {
    int r = blockIdx.x;
    const float* src = (r < HALF) ? (zi + (size_t)r * D) : (zj + (size_t)(r - HALF) * D);
    float x = src[threadIdx.x];
    float s = x * x;
    #pragma unroll
    for (int o = 16; o > 0; o >>= 1) s += __shfl_xor_sync(0xffffffffu, s, o);
    __shared__ float ws[8];
    __shared__ float bc;
    if ((threadIdx.x & 31) == 0) ws[threadIdx.x >> 5] = s;
    __syncthreads();
    if (threadIdx.x == 0) {
        float t = 0.f;
        #pragma unroll
        for (int w = 0; w < 8; w++) t += ws[w];
        bc = rsqrtf(t) * 0.70710678118654752440f;   // * sqrt(1/TEMPERATURE)
    }
    __syncthreads();
    float v = x * bc;
    __nv_bfloat16 hi = __float2bfloat16(v);
    __nv_bfloat16 lo = __float2bfloat16(v - __bfloat162float(hi));
    g_u[(size_t)r * LDU + threadIdx.x]       = hi;
    g_u[(size_t)r * LDU + 256 + threadIdx.x] = lo;
}

// ---------------- kernel 2: mma.sync bf16 split GEMM, kc-major + cp.async ----------------
// 528 blocks, 256 threads (8 warps 2x4), 128x128 tile, warp tile 64x32.
// Per K-chunk (4 of BK=64): async-load Ahi/Alo/Bhi/Blo tiles, run 3 passes
// (hi*hi, hi*lo, lo*hi) from them. A-hi shared by passes 0-1 (global 384->256KB/blk).
// smem tiles (stride 72 bf16 = 144B): Ahi@0 Alo@18432 Bhi@36864 Blo@55296 -> 73728B
// epilogue reuse: smemN[128][68] f32 @0, smemT[64][132] f32 @34816 -> 68608B
#define OFF_AHI 0u
#define OFF_ALO 18432u
#define OFF_BHI 36864u
#define OFF_BLO 55296u
__global__ void __launch_bounds__(256) k_gemm_mma() {
    extern __shared__ char dsm[];
    const uint32_t sbase = smem_u32(dsm);
    float* smemN = (float*)dsm;                          // [128][68]
    float* smemT = (float*)(dsm + 34816);                // [64][132]

    const int tid = threadIdx.x;
    const int wid = tid >> 5;
    const int lane = tid & 31;
    const int wr = wid >> 2;
    const int wc = wid & 3;

    int rem = blockIdx.x;
    int bi = 0;
    while (rem >= NT - bi) { rem -= NT - bi; bi++; }
    const int bj = bi + rem;
    const int i0 = bi * 128, j0 = bj * 128;

    float cc[4][4][4];
    #pragma unroll
    for (int am = 0; am < 4; am++)
        #pragma unroll
        for (int bn = 0; bn < 4; bn++)
            #pragma unroll
            for (int q = 0; q < 4; q++) cc[am][bn][q] = 0.f;

    const int ldr = tid >> 3;
    const int ldc8 = (tid & 7) * 8;

    const uint32_t a_off_lane = (uint32_t)(wr * 64 + (lane & 15)) * 144u + (uint32_t)(lane >> 4) * 16u;
    const int b_nrow = wc * 32 + (lane & 7) + ((lane & 16) ? 8 : 0);
    const uint32_t b_off_lane = (uint32_t)b_nrow * 144u + ((lane & 8) ? 16u : 0u);

    for (int kc = 0; kc < 4; kc++) {
        const int k0 = kc * 64;
        // async-load the 4 tiles for this K-chunk
        #pragma unroll
        for (int it = 0; it < 4; it++) {
            int r = ldr + it * 32;
            uint32_t srow = (uint32_t)(r * 72 + ldc8) * 2u;
            const __nv_bfloat16* gArow = &g_u[(size_t)(i0 + r) * LDU + k0 + ldc8];
            const __nv_bfloat16* gBrow = &g_u[(size_t)(j0 + r) * LDU + k0 + ldc8];
            CP_ASYNC16(sbase + OFF_AHI + srow, gArow);
            CP_ASYNC16(sbase + OFF_ALO + srow, gArow + 256);
            CP_ASYNC16(sbase + OFF_BHI + srow, gBrow);
            CP_ASYNC16(sbase + OFF_BLO + srow, gBrow + 256);
        }
        CP_COMMIT();
        CP_WAIT0();
        __syncthreads();
        // 3 passes from the loaded tiles
        #pragma unroll
        for (int p = 0; p < 3; p++) {
            const uint32_t abase = sbase + ((p == 2) ? OFF_ALO : OFF_AHI) + a_off_lane;
            const uint32_t bbase = sbase + ((p == 1) ? OFF_BLO : OFF_BHI) + b_off_lane;
            #pragma unroll
            for (int kk = 0; kk < 64; kk += 16) {
                uint32_t af[4][4];
                #pragma unroll
                for (int am = 0; am < 4; am++)
                    ldsm4(af[am][0], af[am][1], af[am][2], af[am][3],
                          abase + (uint32_t)(am * 16) * 144u + (uint32_t)kk * 2u);
                uint32_t bf[2][4];
                #pragma unroll
                for (int g = 0; g < 2; g++)
                    ldsm4(bf[g][0], bf[g][1], bf[g][2], bf[g][3],
                          bbase + (uint32_t)(g * 16) * 144u + (uint32_t)kk * 2u);
                #pragma unroll
                for (int am = 0; am < 4; am++)
                    #pragma unroll
                    for (int bn = 0; bn < 4; bn++)
                        mma16816(cc[am][bn], af[am][0], af[am][1], af[am][2], af[am][3],
                                 bf[bn >> 1][(bn & 1) * 2], bf[bn >> 1][(bn & 1) * 2 + 1]);
            }
        }
        __syncthreads();
    }

    // ---- epilogue: two 64-col halves via dual-orientation smem staging ----
    for (int h = 0; h < 2; h++) {
        __syncthreads();
        if ((wc >> 1) == h) {
            #pragma unroll
            for (int am = 0; am < 4; am++) {
                int r = wr * 64 + am * 16 + (lane >> 2);
                #pragma unroll
                for (int bn = 0; bn < 4; bn++) {
                    int c = (wc & 1) * 32 + bn * 8 + (lane & 3) * 2;
                    smemN[r * 68 + c]           = cc[am][bn][0];
                    smemN[r * 68 + c + 1]       = cc[am][bn][1];
                    smemN[(r + 8) * 68 + c]     = cc[am][bn][2];
                    smemN[(r + 8) * 68 + c + 1] = cc[am][bn][3];
                    smemT[c * 132 + r]            = cc[am][bn][0];
                    smemT[(c + 1) * 132 + r]      = cc[am][bn][1];
                    smemT[c * 132 + r + 8]        = cc[am][bn][2];
                    smemT[(c + 1) * 132 + r + 8]  = cc[am][bn][3];
                }
            }
        }
        __syncthreads();
        #pragma unroll
        for (int e = 0; e < 8; e++) {
            int idx = e * 256 + tid;
            int r = idx >> 4;
            int c4 = (idx & 15) * 4;
            float4 v = *(const float4*)&smemN[r * 68 + c4];
            *(float4*)&g_logits[(size_t)(i0 + r) * N + j0 + h * 64 + c4] = v;
        }
        if (bi != bj) {
            #pragma unroll
            for (int e = 0; e < 8; e++) {
                int idx = e * 256 + tid;
                int c = idx >> 5;
                int r4 = (idx & 31) * 4;
                float4 v = *(const float4*)&smemT[c * 132 + r4];
                *(float4*)&g_logits[(size_t)(j0 + h * 64 + c) * N + i0 + r4] = v;
            }
        }
    }
}

// ---------------- kernel 3: per-row COUNTING SORT + suffix-sum + logs ----------------
// dynamic smem layout: ev f32[4096]@0 | srt u32[4096]@16384 | cnt u32[4096]@32768  (48KB)
__device__ __forceinline__ float4 load_label(int k, const float* __restrict__ pi,
                                             const float* __restrict__ pj) {
    const float* p = (k < HALF) ? (pi + (size_t)k * 4) : (pj + (size_t)(k - HALF) * 4);
    return __ldg((const float4*)p);
}

__global__ void __launch_bounds__(1024) k_row(const float* __restrict__ pi,
                                              const float* __restrict__ pj) {
    extern __shared__ char drow[];
    float*    ev  = (float*)drow;                // exp values by original idx
    unsigned* srt = (unsigned*)(drow + 16384);   // sorted composite keys
    unsigned* cnt = (unsigned*)(drow + 32768);   // histogram -> offsets -> cursors -> ends
    __shared__ float redA[32];
    __shared__ float redB[32];
    __shared__ float bcast[3];

    const int i = blockIdx.x;
    const int tid = threadIdx.x;
    const int lane = tid & 31;
    const int warp = tid >> 5;

    // ---- row max + sum ----
    float4 v = *(const float4*)&g_logits[(size_t)i * N + tid * 4];
    float lmax = fmaxf(fmaxf(v.x, v.y), fmaxf(v.z, v.w));
    float lsum = (v.x + v.y) + (v.z + v.w);
    #pragma unroll
    for (int o = 16; o > 0; o >>= 1) {
        lmax = fmaxf(lmax, __shfl_xor_sync(0xffffffffu, lmax, o));
        lsum += __shfl_xor_sync(0xffffffffu, lsum, o);
    }
    if (lane == 0) { redA[warp] = lmax; redB[warp] = lsum; }
    __syncthreads();
    if (warp == 0) {
        float a = redA[lane];
        float b = redB[lane];
        #pragma unroll
        for (int o = 16; o > 0; o >>= 1) {
            a = fmaxf(a, __shfl_xor_sync(0xffffffffu, a, o));
            b += __shfl_xor_sync(0xffffffffu, b, o);
        }
        if (lane == 0) { bcast[0] = a; bcast[1] = b; }
    }
    __syncthreads();
    const float m = bcast[0];
    const float sumAll = bcast[1];

    // ---- build composite keys + exp values; zero histogram ----
    float4 li = load_label(i, pi, pj);
    float lg[4] = {v.x, v.y, v.z, v.w};
    unsigned myk[4];
    #pragma unroll
    for (int q = 0; q < 4; q++) {
        int k = tid * 4 + q;
        if (k == i) {
            bcast[2] = lg[q];
            myk[q] = 0xfffff000u | (unsigned)i;  // key field all-ones (> any real key),
            ev[k] = 0.f;                         // low bits = i so gather reads ev[i] = 0
        } else {
            float4 lk = load_label(k, pi, pj);
            float key = fabsf(li.x - lk.x) + fabsf(li.y - lk.y) +
                        fabsf(li.z - lk.z) + fabsf(li.w - lk.w);
            unsigned ki = (unsigned)(key * 262144.0f);
            ki = min(ki, 1048574u);
            myk[q] = (ki << 12) | (unsigned)k;
            ev[k] = __expf(lg[q] - m);
        }
        cnt[k] = 0u;
    }
    __syncthreads();

    // ---- histogram over top-12-bit buckets ----
    #pragma unroll
    for (int q = 0; q < 4; q++) atomicAdd(&cnt[myk[q] >> 20], 1u);
    __syncthreads();

    // ---- in-place exclusive scan of cnt[4096] (4 per thread) ----
    unsigned c0 = cnt[tid * 4 + 0], c1 = cnt[tid * 4 + 1],
             c2 = cnt[tid * 4 + 2], c3 = cnt[tid * 4 + 3];
    unsigned s = c0 + c1 + c2 + c3;
    unsigned si = s;
    #pragma unroll
    for (int o = 1; o < 32; o <<= 1) {
        unsigned y = __shfl_up_sync(0xffffffffu, si, o);
        if (lane >= o) si += y;
    }
    if (lane == 31) redA[warp] = __uint_as_float(si);
    __syncthreads();
    if (warp == 0) {
        unsigned x = __float_as_uint(redA[lane]);
        unsigned xi = x;
        #pragma unroll
        for (int o = 1; o < 32; o <<= 1) {
            unsigned y = __shfl_up_sync(0xffffffffu, xi, o);
            if (lane >= o) xi += y;
        }
        redB[lane] = __uint_as_float(xi - x);   // exclusive warp base
    }
    __syncthreads();
    unsigned base = __float_as_uint(redB[warp]) + (si - s);
    cnt[tid * 4 + 0] = base;
    cnt[tid * 4 + 1] = base + c0;
    cnt[tid * 4 + 2] = base + c0 + c1;
    cnt[tid * 4 + 3] = base + c0 + c1 + c2;
    __syncthreads();

    // ---- scatter into buckets (cnt becomes per-bucket end offsets) ----
    #pragma unroll
    for (int q = 0; q < 4; q++) {
        unsigned pos = atomicAdd(&cnt[myk[q] >> 20], 1u);
        srt[pos] = myk[q];
    }
    __syncthreads();

    // ---- insertion sort within each tiny bucket (thread t: buckets 4t..4t+3) ----
    #pragma unroll
    for (int q = 0; q < 4; q++) {
        int b = tid * 4 + q;
        int st = (b == 0) ? 0 : (int)cnt[b - 1];
        int en = (int)cnt[b];
        for (int x = st + 1; x < en; x++) {
            unsigned key = srt[x];
            int y = x - 1;
            while (y >= st && srt[y] > key) { srt[y + 1] = srt[y]; y--; }
            srt[y + 1] = key;
        }
    }
    __syncthreads();

    // ---- gather exp in sorted order, suffix-sum, sum of logs ----
    uint4 sw = *(const uint4*)&srt[tid * 4];
    float v0 = ev[sw.x & 0xfffu];
    float v1 = ev[sw.y & 0xfffu];
    float v2 = ev[sw.z & 0xfffu];
    float v3 = ev[sw.w & 0xfffu];
    float s3 = v3;
    float s2 = v2 + s3;
    float s1 = v1 + s2;
    float s0 = v0 + s1;
    float tot = s0;

    float inc = tot;
    #pragma unroll
    for (int o = 1; o < 32; o <<= 1) {
        float y = __shfl_down_sync(0xffffffffu, inc, o);
        if (lane + o < 32) inc += y;
    }
    if (lane == 0) redA[warp] = inc;
    __syncthreads();
    if (warp == 0) {
        float x = redA[lane];
        float i2 = x;
        #pragma unroll
        for (int o = 1; o < 32; o <<= 1) {
            float y = __shfl_down_sync(0xffffffffu, i2, o);
            if (lane + o < 32) i2 += y;
        }
        redB[lane] = i2 - x;
    }
    __syncthreads();
    float excl = (inc - tot) + redB[warp];

    float S0 = s0 + excl;
    float S1 = s1 + excl;
    float S2 = s2 + excl;
    float S3 = s3 + excl;
    float lp = __logf(S0 + EPS) + __logf(S1 + EPS) + __logf(S2 + EPS);
    if (tid * 4 + 3 < N - 1) lp += __logf(S3 + EPS);

    #pragma unroll
    for (int o = 16; o > 0; o >>= 1) lp += __shfl_xor_sync(0xffffffffu, lp, o);
    if (lane == 0) redA[warp] = lp;
    __syncthreads();
    if (warp == 0) {
        float x = redA[lane];
        #pragma unroll
        for (int o = 16; o > 0; o >>= 1) x += __shfl_xor_sync(0xffffffffu, x, o);
        if (lane == 0) {
            float diag = bcast[2];
            float sumlogit = (sumAll - (float)N * m) - (diag - m);
            g_part[i] = sumlogit - x;
        }
    }
}

// ---------------- kernel 4: deterministic final reduce ----------------
__global__ void __launch_bounds__(1024) k_final(float* __restrict__ out) {
    const int tid = threadIdx.x;
    const int lane = tid & 31;
    const int warp = tid >> 5;
    float4 p = *(const float4*)&g_part[tid * 4];
    float s = (p.x + p.y) + (p.z + p.w);
    #pragma unroll
    for (int o = 16; o > 0; o >>= 1) s += __shfl_xor_sync(0xffffffffu, s, o);
    __shared__ float ws[32];
    if (lane == 0) ws[warp] = s;
    __syncthreads();
    if (warp == 0) {
        float x = ws[lane];
        #pragma unroll
        for (int o = 16; o > 0; o >>= 1) x += __shfl_xor_sync(0xffffffffu, x, o);
        if (lane == 0) out[0] = -x / ((float)N * (float)(N - 1));
    }
}

// ---------------- entry ----------------
extern "C" void kernel_launch(void* const* d_in, const int* in_sizes, int n_in,
                              void* d_out, int out_size) {
    const float* zi = (const float*)d_in[0];
    const float* zj = (const float*)d_in[1];
    const float* pi = (const float*)d_in[2];
    const float* pj = (const float*)d_in[3];
    (void)in_sizes; (void)n_in; (void)out_size;

    cudaFuncSetAttribute(k_gemm_mma, cudaFuncAttributeMaxDynamicSharedMemorySize, 73728);
    cudaFuncSetAttribute(k_row, cudaFuncAttributeMaxDynamicSharedMemorySize, 49152);

    k_norm<<<N, 256>>>(zi, zj);
    k_gemm_mma<<<NT * (NT + 1) / 2, 256, 73728>>>();
    k_row<<<N, 1024, 49152>>>(pi, pj);
    k_final<<<1, 1024>>>((float*)d_out);
}